// round 14
// baseline (speedup 1.0000x reference)
#include <cuda_runtime.h>
#include <cuda_bf16.h>
#include <cstdint>

// Problem constants (fixed by the dataset): N=50000, E=800000, D=128.
#define D 128
#define MAXN 65536
#define MAXE 1048576
#define SCAN_B 1024
#define MAXBLK 64

__device__ int   g_deg[MAXN];
__device__ float g_dinv[MAXN];
__device__ int   g_rowStart[MAXN + 1];
__device__ int   g_cursor[MAXN];
__device__ int2  g_csr[MAXE];          // (src, float_as_int(w))
__device__ int   g_blockSums[MAXBLK];
__device__ float g_Wt[128 * 256];      // W^T: [n][k], W = [Wg ; Wl]

// Packed dual-FMA: acc.{lo,hi} += a.{lo,hi} * b.{lo,hi}   (2 fp32 FMAs, 1 instr)
#define FFMA2(acc, a, b) \
    asm("fma.rn.f32x2 %0, %1, %2, %0;" : "+l"(acc) : "l"(a), "l"(b))

__device__ __forceinline__ float lo32(unsigned long long v) {
    return __uint_as_float((uint32_t)v);
}
__device__ __forceinline__ float hi32(unsigned long long v) {
    return __uint_as_float((uint32_t)(v >> 32));
}

// ---------------------------------------------------------------------------
// K1: fused init — build W^T AND deg[i] = 1.
// ---------------------------------------------------------------------------
__global__ void k_init(const float* __restrict__ Wg, const float* __restrict__ Wl,
                       int N) {
    int i = blockIdx.x * blockDim.x + threadIdx.x;
    if (i < 128 * 256) {
        int k = i >> 7;
        int n = i & 127;
        float v = (k < 128) ? Wg[k * 128 + n] : Wl[(k - 128) * 128 + n];
        g_Wt[n * 256 + k] = v;
    }
    if (i < N) g_deg[i] = 1;
}

// ---------------------------------------------------------------------------
// K2: deg[dst[e]] += 1
// ---------------------------------------------------------------------------
__global__ void k_deg_count(const int* __restrict__ adj, int E) {
    int e = blockIdx.x * blockDim.x + threadIdx.x;
    if (e < E) atomicAdd(&g_deg[adj[E + e]], 1);
}

// ---------------------------------------------------------------------------
// K3a: per-block exclusive scan of (deg-1); dinv fused.
// ---------------------------------------------------------------------------
__global__ void __launch_bounds__(SCAN_B) k_scan_partial(int N) {
    __shared__ int wsum[32];
    int tid = threadIdx.x, lane = tid & 31, wid = tid >> 5;
    int i = blockIdx.x * SCAN_B + tid;
    int deg = (i < N) ? g_deg[i] : 1;
    if (i < N) g_dinv[i] = rsqrtf((float)deg);
    int v = deg - 1;
    int inc = v;
    #pragma unroll
    for (int o = 1; o < 32; o <<= 1) {
        int t = __shfl_up_sync(0xFFFFFFFFu, inc, o);
        if (lane >= o) inc += t;
    }
    if (lane == 31) wsum[wid] = inc;
    __syncthreads();
    if (wid == 0) {
        int w = wsum[lane];
        int winc = w;
        #pragma unroll
        for (int o = 1; o < 32; o <<= 1) {
            int t = __shfl_up_sync(0xFFFFFFFFu, winc, o);
            if (lane >= o) winc += t;
        }
        wsum[lane] = winc - w;
        if (lane == 31) g_blockSums[blockIdx.x] = winc;
    }
    __syncthreads();
    if (i < N) g_rowStart[i] = wsum[wid] + (inc - v);
}

// ---------------------------------------------------------------------------
// K3b: add block offsets (each block warp-reduces its own prefix of the
//      <=64 block sums — scan_mid fused away); write rowStart + cursor.
// ---------------------------------------------------------------------------
__global__ void __launch_bounds__(SCAN_B) k_scan_add(int N, int E) {
    __shared__ int s_off;
    int tid = threadIdx.x;
    if (tid < 32) {
        int sum = 0;
        for (int b = tid; b < blockIdx.x; b += 32) sum += g_blockSums[b];
        #pragma unroll
        for (int o = 16; o > 0; o >>= 1)
            sum += __shfl_xor_sync(0xFFFFFFFFu, sum, o);
        if (tid == 0) s_off = sum;
    }
    __syncthreads();
    int i = blockIdx.x * SCAN_B + tid;
    if (i < N) {
        int val = g_rowStart[i] + s_off;
        g_rowStart[i] = val;
        g_cursor[i]   = val;
    }
    if (i == 0) g_rowStart[N] = E;
}

// ---------------------------------------------------------------------------
// K4: fill CSR (combined (src, w) int2 -> single STG.64)
// ---------------------------------------------------------------------------
__global__ void k_fill(const int* __restrict__ adj, int E) {
    int e = blockIdx.x * blockDim.x + threadIdx.x;
    if (e >= E) return;
    int s = __ldg(&adj[e]);
    int t = __ldg(&adj[E + e]);
    float w = g_dinv[s] * g_dinv[t];
    int pos = atomicAdd(&g_cursor[t], 1);
    g_csr[pos] = make_int2(s, __float_as_int(w));
}

// ---------------------------------------------------------------------------
// K5: FUSED aggregation + GEMM (K=256) + bias + eps + LayerNorm.
//
// Phase 1: warp-per-node CSR gather -> Agg smem tile [64][128] (32KB).
//          Xs tile [64][128] staged from x (32KB).
// Phase 2: FFMA2 mainloop (acc lo = even-k sum, hi = odd-k sum).
//          A chunks kc<2 read from Agg, kc>=2 from Xs (both smem, broadcast).
//          Wt chunk [128][64] XOR-swizzled (32KB), restaged per chunk.
//
// Block: 256 threads, tile = 64 rows x 128 cols; thread = 8 rows x 4 cols.
// Dynamic smem: 96KB -> 2 blocks/SM; block A's gather overlaps block B's fma.
// ---------------------------------------------------------------------------
#define BM 64
#define KC 64
#define SM_AGG 0
#define SM_XS  32768
#define SM_WT  65536
#define GEMM_SMEM 98304

__global__ void __launch_bounds__(256, 2)
k_gemm_fused(const float4* __restrict__ x4,
             const float* __restrict__ x,
             const float* __restrict__ bias,
             const float* __restrict__ lnw,
             const float* __restrict__ lnb,
             float* __restrict__ out, int N) {
    extern __shared__ char sm[];
    float* Agg          = (float*)(sm + SM_AGG);   // [64][128]
    float* Xs           = (float*)(sm + SM_XS);    // [64][128]
    float (*Wt_s)[KC]   = (float(*)[KC])(sm + SM_WT);  // [128][64]

    int tid  = threadIdx.x;
    int tx   = tid & 31;
    int ty   = tid >> 5;
    int row0 = blockIdx.x * BM;
    int sw   = tx & 7;

    // ---- phase 0: stage Xs (x rows, full K=128) ----
    #pragma unroll
    for (int g = 0; g < 8; g++) {
        int i  = tid + g * 256;       // 0..2047 float4s
        int r  = i >> 5;
        int c4 = i & 31;
        int row = row0 + r;
        float4 v = make_float4(0.f, 0.f, 0.f, 0.f);
        if (row < N) v = x4[row * 32 + c4];
        *(float4*)&Xs[r * D + c4 * 4] = v;
    }

    // ---- phase 1: aggregation, warp-per-node, 8 nodes per warp ----
    #pragma unroll 1
    for (int j = 0; j < 8; j++) {
        int r    = ty * 8 + j;
        int node = row0 + r;
        float4 acc0 = make_float4(0.f, 0.f, 0.f, 0.f);
        if (node < N) {
            float dv = g_dinv[node];
            float w0 = dv * dv;
            float4 v = x4[node * 32 + tx];
            acc0 = make_float4(v.x * w0, v.y * w0, v.z * w0, v.w * w0);
            float4 acc1 = make_float4(0.f, 0.f, 0.f, 0.f);
            int beg = g_rowStart[node];
            int end = g_rowStart[node + 1];
            int i = beg;
            for (; i + 1 < end; i += 2) {
                int2 e0 = g_csr[i];
                int2 e1 = g_csr[i + 1];
                float w0e = __int_as_float(e0.y);
                float w1e = __int_as_float(e1.y);
                float4 a = x4[e0.x * 32 + tx];
                float4 b = x4[e1.x * 32 + tx];
                acc0.x = fmaf(w0e, a.x, acc0.x); acc0.y = fmaf(w0e, a.y, acc0.y);
                acc0.z = fmaf(w0e, a.z, acc0.z); acc0.w = fmaf(w0e, a.w, acc0.w);
                acc1.x = fmaf(w1e, b.x, acc1.x); acc1.y = fmaf(w1e, b.y, acc1.y);
                acc1.z = fmaf(w1e, b.z, acc1.z); acc1.w = fmaf(w1e, b.w, acc1.w);
            }
            if (i < end) {
                int2 e0 = g_csr[i];
                float we = __int_as_float(e0.y);
                float4 a = x4[e0.x * 32 + tx];
                acc0.x = fmaf(we, a.x, acc0.x); acc0.y = fmaf(we, a.y, acc0.y);
                acc0.z = fmaf(we, a.z, acc0.z); acc0.w = fmaf(we, a.w, acc0.w);
            }
            acc0.x += acc1.x; acc0.y += acc1.y;
            acc0.z += acc1.z; acc0.w += acc1.w;
        }
        *(float4*)&Agg[r * D + tx * 4] = acc0;
    }

    // ---- phase 2: GEMM mainloop ----
    unsigned long long acc[8][4];
    #pragma unroll
    for (int rr = 0; rr < 8; rr++)
        #pragma unroll
        for (int jj = 0; jj < 4; jj++) acc[rr][jj] = 0ull;

    #pragma unroll 1
    for (int kc = 0; kc < 4; kc++) {
        int k0 = kc * KC;
        __syncthreads();
        // stage Wt chunk: 128 cols x 16 units of 4k, XOR-swizzled
        #pragma unroll
        for (int g = 0; g < 8; g++) {
            int i   = tid + g * 256;      // 0..2047
            int col = i >> 4;
            int u   = i & 15;
            float4 v = *(const float4*)(g_Wt + col * 256 + k0 + u * 4);
            int phys = u ^ ((col >> 2) & 7);
            *(float4*)&Wt_s[col][phys * 4] = v;
        }
        __syncthreads();

        const float* Asrc = (kc < 2) ? Agg : Xs;
        int kofs = (kc & 1) * KC;

        #pragma unroll 4
        for (int u = 0; u < 16; u++) {
            int pu = (u ^ sw) * 4;
            ulonglong2 wv0 = *(const ulonglong2*)&Wt_s[tx * 4 + 0][pu];
            ulonglong2 wv1 = *(const ulonglong2*)&Wt_s[tx * 4 + 1][pu];
            ulonglong2 wv2 = *(const ulonglong2*)&Wt_s[tx * 4 + 2][pu];
            ulonglong2 wv3 = *(const ulonglong2*)&Wt_s[tx * 4 + 3][pu];
            #pragma unroll
            for (int rr = 0; rr < 8; rr++) {
                ulonglong2 av = *(const ulonglong2*)&Asrc[(ty * 8 + rr) * D + kofs + u * 4];
                FFMA2(acc[rr][0], av.x, wv0.x); FFMA2(acc[rr][0], av.y, wv0.y);
                FFMA2(acc[rr][1], av.x, wv1.x); FFMA2(acc[rr][1], av.y, wv1.y);
                FFMA2(acc[rr][2], av.x, wv2.x); FFMA2(acc[rr][2], av.y, wv2.y);
                FFMA2(acc[rr][3], av.x, wv3.x); FFMA2(acc[rr][3], av.y, wv3.y);
            }
        }
    }

    // ---- epilogue: unpack (lo=even-k, hi=odd-k), bias+eps, LayerNorm ----
    float4 bv  = ((const float4*)bias)[tx];
    float4 lwv = ((const float4*)lnw)[tx];
    float4 lbv = ((const float4*)lnb)[tx];

    #pragma unroll
    for (int rr = 0; rr < 8; rr++) {
        int row = row0 + ty * 8 + rr;
        float c0 = lo32(acc[rr][0]) + hi32(acc[rr][0]) + bv.x + 1e-6f;
        float c1 = lo32(acc[rr][1]) + hi32(acc[rr][1]) + bv.y + 1e-6f;
        float c2 = lo32(acc[rr][2]) + hi32(acc[rr][2]) + bv.z + 1e-6f;
        float c3 = lo32(acc[rr][3]) + hi32(acc[rr][3]) + bv.w + 1e-6f;
        float s  = c0 + c1 + c2 + c3;
        float s2 = c0 * c0 + c1 * c1 + c2 * c2 + c3 * c3;
        #pragma unroll
        for (int off = 16; off > 0; off >>= 1) {
            s  += __shfl_xor_sync(0xFFFFFFFFu, s,  off);
            s2 += __shfl_xor_sync(0xFFFFFFFFu, s2, off);
        }
        float mu   = s * (1.0f / D);
        float var  = fmaxf(s2 * (1.0f / D) - mu * mu, 0.0f);
        float rstd = rsqrtf(var + 1e-5f);
        if (row < N) {
            float4 o;
            o.x = (c0 - mu) * rstd * lwv.x + lbv.x;
            o.y = (c1 - mu) * rstd * lwv.y + lbv.y;
            o.z = (c2 - mu) * rstd * lwv.z + lbv.z;
            o.w = (c3 - mu) * rstd * lwv.w + lbv.w;
            ((float4*)(out + (size_t)row * D))[tx] = o;
        }
    }
}

// ---------------------------------------------------------------------------
extern "C" void kernel_launch(void* const* d_in, const int* in_sizes, int n_in,
                              void* d_out, int out_size) {
    const int*   adj = (const int*)d_in[0];
    const float* x   = (const float*)d_in[1];
    const float* Wg  = (const float*)d_in[2];
    const float* bg  = (const float*)d_in[3];
    const float* Wl  = (const float*)d_in[4];
    const float* lnw = (const float*)d_in[5];
    const float* lnb = (const float*)d_in[6];
    float*       out = (float*)d_out;

    int E = in_sizes[0] / 2;
    int N = in_sizes[1] / D;
    int nb = (N + SCAN_B - 1) / SCAN_B;
    int initThreads = (128 * 256 > N) ? 128 * 256 : N;

    cudaFuncSetAttribute(k_gemm_fused, cudaFuncAttributeMaxDynamicSharedMemorySize,
                         GEMM_SMEM);

    k_init<<<(initThreads + 255) / 256, 256>>>(Wg, Wl, N);
    k_deg_count<<<(E + 255) / 256, 256>>>(adj, E);
    k_scan_partial<<<nb, SCAN_B>>>(N);
    k_scan_add<<<nb, SCAN_B>>>(N, E);
    k_fill<<<(E + 255) / 256, 256>>>(adj, E);

    int gemmBlocks = (N + BM - 1) / BM;
    k_gemm_fused<<<gemmBlocks, 256, GEMM_SMEM>>>((const float4*)x, x, bg, lnw,
                                                 lnb, out, N);
}

// round 15
// speedup vs baseline: 2.3209x; 2.3209x over previous
#include <cuda_runtime.h>
#include <cuda_bf16.h>
#include <cstdint>

// Problem constants (fixed by the dataset): N=50000, E=800000, D=128.
#define D 128
#define MAXN 65536
#define MAXE 1048576
#define SCAN_B 1024
#define MAXBLK 64

__device__ int   g_deg[MAXN];
__device__ float g_dinv[MAXN];
__device__ int   g_rowStart[MAXN + 1];
__device__ int   g_cursor[MAXN];
__device__ int2  g_csr[MAXE];          // (src, float_as_int(w))
__device__ int   g_blockSums[MAXBLK];
// W^T = [Wg ; Wl]^T as [n][k] bf16 hi/lo split (n=128 rows, k=256 cols)
__device__ __nv_bfloat16 g_Wthi[128 * 256];
__device__ __nv_bfloat16 g_Wtlo[128 * 256];

__device__ __forceinline__ uint32_t smem_u32(const void* p) {
    uint32_t a;
    asm("{ .reg .u64 t; cvta.to.shared.u64 t, %1; cvt.u32.u64 %0, t; }"
        : "=r"(a) : "l"(p));
    return a;
}
__device__ __forceinline__ void ldsm_x4(uint32_t& r0, uint32_t& r1,
                                        uint32_t& r2, uint32_t& r3,
                                        uint32_t addr) {
    asm volatile("ldmatrix.sync.aligned.m8n8.x4.shared.b16 {%0,%1,%2,%3}, [%4];"
                 : "=r"(r0), "=r"(r1), "=r"(r2), "=r"(r3) : "r"(addr));
}
__device__ __forceinline__ void mma_bf16(float* c, uint32_t a0, uint32_t a1,
                                         uint32_t a2, uint32_t a3,
                                         uint32_t b0, uint32_t b1) {
    asm volatile(
        "mma.sync.aligned.m16n8k16.row.col.f32.bf16.bf16.f32 "
        "{%0,%1,%2,%3}, {%4,%5,%6,%7}, {%8,%9}, {%0,%1,%2,%3};"
        : "+f"(c[0]), "+f"(c[1]), "+f"(c[2]), "+f"(c[3])
        : "r"(a0), "r"(a1), "r"(a2), "r"(a3), "r"(b0), "r"(b1));
}
__device__ __forceinline__ uint32_t pack_bf16_hi(float a, float b,
                                                 uint32_t& lo) {
    __nv_bfloat16 ha = __float2bfloat16_rn(a);
    __nv_bfloat16 hb = __float2bfloat16_rn(b);
    float la = a - __bfloat162float(ha);
    float lb = b - __bfloat162float(hb);
    __nv_bfloat162 hp; hp.x = ha; hp.y = hb;
    __nv_bfloat162 lp = __floats2bfloat162_rn(la, lb);
    lo = *(uint32_t*)&lp;
    return *(uint32_t*)&hp;
}

// ---------------------------------------------------------------------------
// K1: fused init — build W^T bf16 hi/lo AND deg[i] = 1.
// ---------------------------------------------------------------------------
__global__ void k_init(const float* __restrict__ Wg, const float* __restrict__ Wl,
                       int N) {
    int i = blockIdx.x * blockDim.x + threadIdx.x;
    if (i < 128 * 256) {
        int k = i >> 7;
        int n = i & 127;
        float v = (k < 128) ? Wg[k * 128 + n] : Wl[(k - 128) * 128 + n];
        __nv_bfloat16 h = __float2bfloat16_rn(v);
        g_Wthi[n * 256 + k] = h;
        g_Wtlo[n * 256 + k] = __float2bfloat16_rn(v - __bfloat162float(h));
    }
    if (i < N) g_deg[i] = 1;
}

// ---------------------------------------------------------------------------
// K2: deg[dst[e]] += 1
// ---------------------------------------------------------------------------
__global__ void k_deg_count(const int* __restrict__ adj, int E) {
    int e = blockIdx.x * blockDim.x + threadIdx.x;
    if (e < E) atomicAdd(&g_deg[adj[E + e]], 1);
}

// ---------------------------------------------------------------------------
// K3a: per-block exclusive scan of (deg-1); dinv fused.
// ---------------------------------------------------------------------------
__global__ void __launch_bounds__(SCAN_B) k_scan_partial(int N) {
    __shared__ int wsum[32];
    int tid = threadIdx.x, lane = tid & 31, wid = tid >> 5;
    int i = blockIdx.x * SCAN_B + tid;
    int deg = (i < N) ? g_deg[i] : 1;
    if (i < N) g_dinv[i] = rsqrtf((float)deg);
    int v = deg - 1;
    int inc = v;
    #pragma unroll
    for (int o = 1; o < 32; o <<= 1) {
        int t = __shfl_up_sync(0xFFFFFFFFu, inc, o);
        if (lane >= o) inc += t;
    }
    if (lane == 31) wsum[wid] = inc;
    __syncthreads();
    if (wid == 0) {
        int w = wsum[lane];
        int winc = w;
        #pragma unroll
        for (int o = 1; o < 32; o <<= 1) {
            int t = __shfl_up_sync(0xFFFFFFFFu, winc, o);
            if (lane >= o) winc += t;
        }
        wsum[lane] = winc - w;
        if (lane == 31) g_blockSums[blockIdx.x] = winc;
    }
    __syncthreads();
    if (i < N) g_rowStart[i] = wsum[wid] + (inc - v);
}

// ---------------------------------------------------------------------------
// K3b: exclusive scan of block sums — single warp, shuffle scan (nb <= 64).
// ---------------------------------------------------------------------------
__global__ void k_scan_mid(int nb) {
    int lane = threadIdx.x;
    int a = (lane < nb) ? g_blockSums[lane] : 0;
    int b = (lane + 32 < nb) ? g_blockSums[lane + 32] : 0;
    int ia = a, ib = b;
    #pragma unroll
    for (int o = 1; o < 32; o <<= 1) {
        int t = __shfl_up_sync(0xFFFFFFFFu, ia, o);
        if (lane >= o) ia += t;
        int u = __shfl_up_sync(0xFFFFFFFFu, ib, o);
        if (lane >= o) ib += u;
    }
    int totA = __shfl_sync(0xFFFFFFFFu, ia, 31);
    if (lane < nb)      g_blockSums[lane]      = ia - a;
    if (lane + 32 < nb) g_blockSums[lane + 32] = ib - b + totA;
}

// ---------------------------------------------------------------------------
// K3c: add block offsets; write rowStart + cursor; rowStart[N] = E.
// ---------------------------------------------------------------------------
__global__ void __launch_bounds__(SCAN_B) k_scan_add(int N, int E) {
    int i = blockIdx.x * SCAN_B + threadIdx.x;
    if (i < N) {
        int val = g_rowStart[i] + g_blockSums[blockIdx.x];
        g_rowStart[i] = val;
        g_cursor[i]   = val;
    }
    if (i == 0) g_rowStart[N] = E;
}

// ---------------------------------------------------------------------------
// K4: fill CSR (combined (src, w) int2 -> single STG.64)
// ---------------------------------------------------------------------------
__global__ void k_fill(const int* __restrict__ adj, int E) {
    int e = blockIdx.x * blockDim.x + threadIdx.x;
    if (e >= E) return;
    int s = __ldg(&adj[e]);
    int t = __ldg(&adj[E + e]);
    float w = g_dinv[s] * g_dinv[t];
    int pos = atomicAdd(&g_cursor[t], 1);
    g_csr[pos] = make_int2(s, __float_as_int(w));
}

// ---------------------------------------------------------------------------
// K5: aggregation by gather — one warp per node (high occupancy, high MLP).
// ---------------------------------------------------------------------------
__global__ void __launch_bounds__(256) k_agg(const float4* __restrict__ x4,
                                             float4* __restrict__ out4, int N) {
    int gt   = blockIdx.x * blockDim.x + threadIdx.x;
    int node = gt >> 5;
    int lane = gt & 31;
    if (node >= N) return;

    float dv = g_dinv[node];
    float4 v = x4[node * 32 + lane];
    float w0 = dv * dv;
    float4 acc0 = make_float4(v.x * w0, v.y * w0, v.z * w0, v.w * w0);
    float4 acc1 = make_float4(0.f, 0.f, 0.f, 0.f);

    int beg = g_rowStart[node];
    int end = g_rowStart[node + 1];

    int i = beg;
    for (; i + 1 < end; i += 2) {
        int2 e0 = g_csr[i];
        int2 e1 = g_csr[i + 1];
        float w0e = __int_as_float(e0.y);
        float w1e = __int_as_float(e1.y);
        float4 a = x4[e0.x * 32 + lane];
        float4 b = x4[e1.x * 32 + lane];
        acc0.x = fmaf(w0e, a.x, acc0.x); acc0.y = fmaf(w0e, a.y, acc0.y);
        acc0.z = fmaf(w0e, a.z, acc0.z); acc0.w = fmaf(w0e, a.w, acc0.w);
        acc1.x = fmaf(w1e, b.x, acc1.x); acc1.y = fmaf(w1e, b.y, acc1.y);
        acc1.z = fmaf(w1e, b.z, acc1.z); acc1.w = fmaf(w1e, b.w, acc1.w);
    }
    if (i < end) {
        int2 e0 = g_csr[i];
        float we = __int_as_float(e0.y);
        float4 a = x4[e0.x * 32 + lane];
        acc0.x = fmaf(we, a.x, acc0.x); acc0.y = fmaf(we, a.y, acc0.y);
        acc0.z = fmaf(we, a.z, acc0.z); acc0.w = fmaf(we, a.w, acc0.w);
    }
    acc0.x += acc1.x; acc0.y += acc1.y; acc0.z += acc1.z; acc0.w += acc1.w;
    out4[node * 32 + lane] = acc0;
}

// ---------------------------------------------------------------------------
// K6: HMMA GEMM (K=256: [aggx | x] @ Wt^T) + bias + eps + LayerNorm.
//   mma.sync.m16n8k16 bf16 with hi/lo error-compensated split:
//   D ~= Ah*Bh + Ah*Bl + Al*Bh (fp32 accumulate).
//   Block: 256 thr (8 warps), tile 128 rows x 128 cols, 4 K-chunks of 64.
//   Warp owns 16 FULL rows (1 m16 x 16 n8) -> LN reduces in a lane quad.
//   Smem: Ah|Al|Bh|Bl each [128][64] bf16 (16KB) = 64KB, unit-XOR swizzle.
// ---------------------------------------------------------------------------
#define GEMM_SMEM 65536

__global__ void __launch_bounds__(256, 2)
k_gemm_hmma(const float* __restrict__ x,
            const float* __restrict__ bias,
            const float* __restrict__ lnw,
            const float* __restrict__ lnb,
            float* __restrict__ out, int N) {
    extern __shared__ char sm[];
    __shared__ float s_b[128], s_w[128], s_bb[128];

    const uint32_t sbase = smem_u32(sm);
    const uint32_t AHo = 0, ALo = 16384, BHo = 32768, BLo = 49152;

    int tid  = threadIdx.x;
    int lane = tid & 31;
    int warp = tid >> 5;
    int row0 = blockIdx.x * 128;
    int wrow0 = warp * 16;

    if (tid < 128) {
        s_b[tid]  = bias[tid];
        s_w[tid]  = lnw[tid];
        s_bb[tid] = lnb[tid];
    }

    float acc[16][4];
    #pragma unroll
    for (int nt = 0; nt < 16; nt++)
        #pragma unroll
        for (int j = 0; j < 4; j++) acc[nt][j] = 0.f;

    #pragma unroll 1
    for (int kc = 0; kc < 4; kc++) {
        __syncthreads();
        // ---- stage A chunk: 128 rows x 64 k, fp32 -> bf16 hi/lo ----
        {
            const float* Asrc = (kc < 2) ? out : x;   // k<128 -> aggx (in out)
            int kofs = (kc & 1) * 64;
            #pragma unroll
            for (int g = tid; g < 1024; g += 256) {
                int r = g >> 3, u = g & 7;
                int grow = row0 + r;
                float4 v0 = make_float4(0.f, 0.f, 0.f, 0.f), v1 = v0;
                if (grow < N) {
                    const float4* p =
                        (const float4*)(Asrc + (size_t)grow * 128 + kofs + u * 8);
                    v0 = p[0]; v1 = p[1];
                }
                uint32_t h0, h1, h2, h3, l0, l1, l2, l3;
                h0 = pack_bf16_hi(v0.x, v0.y, l0);
                h1 = pack_bf16_hi(v0.z, v0.w, l1);
                h2 = pack_bf16_hi(v1.x, v1.y, l2);
                h3 = pack_bf16_hi(v1.z, v1.w, l3);
                uint32_t off = r * 128 + ((u ^ (r & 7)) * 16);
                *(uint4*)(sm + AHo + off) = make_uint4(h0, h1, h2, h3);
                *(uint4*)(sm + ALo + off) = make_uint4(l0, l1, l2, l3);
            }
        }
        // ---- stage B chunk from precomputed W^T hi/lo ----
        #pragma unroll
        for (int g = tid; g < 1024; g += 256) {
            int n = g >> 3, u = g & 7;
            uint4 vh = *(const uint4*)(g_Wthi + n * 256 + kc * 64 + u * 8);
            uint4 vl = *(const uint4*)(g_Wtlo + n * 256 + kc * 64 + u * 8);
            uint32_t off = n * 128 + ((u ^ (n & 7)) * 16);
            *(uint4*)(sm + BHo + off) = vh;
            *(uint4*)(sm + BLo + off) = vl;
        }
        __syncthreads();

        // ---- mainloop: 4 k16 steps ----
        #pragma unroll
        for (int ks = 0; ks < 4; ks++) {
            int ko = ks * 16;
            // A frags (m16k16): rows wrow0..+15
            int ar = wrow0 + (lane & 15);
            uint32_t au = (uint32_t)((ko >> 3) + (lane >> 4));
            uint32_t aoff = ar * 128 + ((au ^ (ar & 7)) * 16);
            uint32_t ah0, ah1, ah2, ah3, al0, al1, al2, al3;
            ldsm_x4(ah0, ah1, ah2, ah3, sbase + AHo + aoff);
            ldsm_x4(al0, al1, al2, al3, sbase + ALo + aoff);
            // B: 8 n16 tiles
            #pragma unroll
            for (int j = 0; j < 8; j++) {
                int nr = j * 16 + (lane & 15);
                uint32_t bu = (uint32_t)((ko >> 3) + (lane >> 4));
                uint32_t boff = nr * 128 + ((bu ^ (nr & 7)) * 16);
                uint32_t bh0, bh1, bh2, bh3, bl0, bl1, bl2, bl3;
                ldsm_x4(bh0, bh1, bh2, bh3, sbase + BHo + boff);
                ldsm_x4(bl0, bl1, bl2, bl3, sbase + BLo + boff);
                // n8 tile 2j:   B frag (r0, r2); tile 2j+1: (r1, r3)
                mma_bf16(acc[2 * j],     ah0, ah1, ah2, ah3, bh0, bh2);
                mma_bf16(acc[2 * j],     ah0, ah1, ah2, ah3, bl0, bl2);
                mma_bf16(acc[2 * j],     al0, al1, al2, al3, bh0, bh2);
                mma_bf16(acc[2 * j + 1], ah0, ah1, ah2, ah3, bh1, bh3);
                mma_bf16(acc[2 * j + 1], ah0, ah1, ah2, ah3, bl1, bl3);
                mma_bf16(acc[2 * j + 1], al0, al1, al2, al3, bh1, bh3);
            }
        }
    }

    // ---- epilogue: bias + eps, LayerNorm per row, write out ----
    // Lane holds rows r0 = wrow0 + (lane>>2) and r1 = r0 + 8;
    // cols nt*8 + (lane&3)*2 + {0,1}: acc[nt][0..1] (r0), acc[nt][2..3] (r1).
    float s0 = 0.f, q0 = 0.f, s1 = 0.f, q1 = 0.f;
    #pragma unroll
    for (int nt = 0; nt < 16; nt++) {
        int c = nt * 8 + (lane & 3) * 2;
        float b0 = s_b[c] + 1e-6f, b1 = s_b[c + 1] + 1e-6f;
        acc[nt][0] += b0; acc[nt][1] += b1;
        acc[nt][2] += b0; acc[nt][3] += b1;
        s0 += acc[nt][0] + acc[nt][1];
        q0 += acc[nt][0] * acc[nt][0] + acc[nt][1] * acc[nt][1];
        s1 += acc[nt][2] + acc[nt][3];
        q1 += acc[nt][2] * acc[nt][2] + acc[nt][3] * acc[nt][3];
    }
    #pragma unroll
    for (int off = 1; off <= 2; off <<= 1) {
        s0 += __shfl_xor_sync(0xFFFFFFFFu, s0, off);
        q0 += __shfl_xor_sync(0xFFFFFFFFu, q0, off);
        s1 += __shfl_xor_sync(0xFFFFFFFFu, s1, off);
        q1 += __shfl_xor_sync(0xFFFFFFFFu, q1, off);
    }
    float mu0   = s0 * (1.0f / D);
    float var0  = fmaxf(q0 * (1.0f / D) - mu0 * mu0, 0.0f);
    float rstd0 = rsqrtf(var0 + 1e-5f);
    float mu1   = s1 * (1.0f / D);
    float var1  = fmaxf(q1 * (1.0f / D) - mu1 * mu1, 0.0f);
    float rstd1 = rsqrtf(var1 + 1e-5f);

    int r0g = row0 + wrow0 + (lane >> 2);
    int r1g = r0g + 8;
    #pragma unroll
    for (int nt = 0; nt < 16; nt++) {
        int c = nt * 8 + (lane & 3) * 2;
        float w0v = s_w[c], w1v = s_w[c + 1];
        float bb0 = s_bb[c], bb1 = s_bb[c + 1];
        if (r0g < N) {
            float2 o;
            o.x = (acc[nt][0] - mu0) * rstd0 * w0v + bb0;
            o.y = (acc[nt][1] - mu0) * rstd0 * w1v + bb1;
            *(float2*)(out + (size_t)r0g * D + c) = o;
        }
        if (r1g < N) {
            float2 o;
            o.x = (acc[nt][2] - mu1) * rstd1 * w0v + bb0;
            o.y = (acc[nt][3] - mu1) * rstd1 * w1v + bb1;
            *(float2*)(out + (size_t)r1g * D + c) = o;
        }
    }
}

// ---------------------------------------------------------------------------
extern "C" void kernel_launch(void* const* d_in, const int* in_sizes, int n_in,
                              void* d_out, int out_size) {
    const int*   adj = (const int*)d_in[0];
    const float* x   = (const float*)d_in[1];
    const float* Wg  = (const float*)d_in[2];
    const float* bg  = (const float*)d_in[3];
    const float* Wl  = (const float*)d_in[4];
    const float* lnw = (const float*)d_in[5];
    const float* lnb = (const float*)d_in[6];
    float*       out = (float*)d_out;

    int E = in_sizes[0] / 2;
    int N = in_sizes[1] / D;
    int nb = (N + SCAN_B - 1) / SCAN_B;
    int initThreads = (128 * 256 > N) ? 128 * 256 : N;

    cudaFuncSetAttribute(k_gemm_hmma, cudaFuncAttributeMaxDynamicSharedMemorySize,
                         GEMM_SMEM);

    k_init<<<(initThreads + 255) / 256, 256>>>(Wg, Wl, N);
    k_deg_count<<<(E + 255) / 256, 256>>>(adj, E);
    k_scan_partial<<<nb, SCAN_B>>>(N);
    k_scan_mid<<<1, 32>>>(nb);
    k_scan_add<<<nb, SCAN_B>>>(N, E);
    k_fill<<<(E + 255) / 256, 256>>>(adj, E);

    int aggThreads = N * 32;
    k_agg<<<(aggThreads + 255) / 256, 256>>>((const float4*)x, (float4*)out, N);

    int gemmBlocks = (N + 127) / 128;
    k_gemm_hmma<<<gemmBlocks, 256, GEMM_SMEM>>>(x, bg, lnw, lnb, out, N);
}